// round 1
// baseline (speedup 1.0000x reference)
#include <cuda_runtime.h>

#define BB 8
#define LL 2048
#define DD 1024
#define HH 120
#define HP 128
#define LOG2E 1.44269504088896340736f

// Scratch (device globals; no allocs allowed)
__device__ float g_WeffT[HP * DD];   // [128][1024]  (q_weight^T @ W)^T, zero-padded rows 120..127
__device__ float g_beff[HP];         // bias @ W, zero-padded
__device__ float g_y[BB * LL * HP];  // projected context, padded cols are exactly 0
__device__ float g_norm[BB * LL];    // ||y_i||^2
__device__ float g_rowsum[BB * LL];  // softmax denominators

static __device__ __forceinline__ void fma2(unsigned long long &c,
                                            unsigned long long a,
                                            unsigned long long b) {
    asm("fma.rn.f32x2 %0, %1, %2, %0;" : "+l"(c) : "l"(a), "l"(b));
}
static __device__ __forceinline__ float ex2(float x) {
    float r; asm("ex2.approx.ftz.f32 %0, %1;" : "=f"(r) : "f"(x)); return r;
}
static __device__ __forceinline__ float lo32(unsigned long long v) {
    return __uint_as_float((unsigned)(v & 0xffffffffull));
}
static __device__ __forceinline__ float hi32(unsigned long long v) {
    return __uint_as_float((unsigned)(v >> 32));
}

// ---------------------------------------------------------------------------
// Kernel 1: WeffT[j][d] = sum_h qW[h][d] * W[h][j];  beff[j] = sum_h qb[h]*W[h][j]
// grid 128 blocks (j), 256 threads
// ---------------------------------------------------------------------------
__global__ void prep_kernel(const float* __restrict__ qw,
                            const float* __restrict__ qb,
                            const float* __restrict__ W) {
    int j = blockIdx.x;
    int tid = threadIdx.x;
    __shared__ float sw[HH];
    if (j < HH && tid < HH) sw[tid] = W[tid * HH + j];
    __syncthreads();

    if (j >= HH) {  // zero padding
        #pragma unroll
        for (int it = 0; it < 4; ++it) g_WeffT[j * DD + tid + it * 256] = 0.f;
        if (tid == 0) g_beff[j] = 0.f;
        return;
    }
    #pragma unroll
    for (int it = 0; it < 4; ++it) {
        int d = tid + it * 256;
        float acc = 0.f;
        #pragma unroll 8
        for (int h = 0; h < HH; ++h) acc += qw[h * DD + d] * sw[h];
        g_WeffT[j * DD + d] = acc;
    }
    if (tid == 0) {
        float acc = 0.f;
        for (int h = 0; h < HH; ++h) acc += qb[h] * sw[h];
        g_beff[j] = acc;
    }
}

// ---------------------------------------------------------------------------
// Kernel 2: y = q @ WeffT^T + beff  (M=16384, N=128, K=1024), plus row norms.
// CTA: 64 rows x 128 cols, 256 threads. Warp w -> rows w*8+i, lane l -> cols l+32*jj.
// fp32x2 FMAs pair adjacent k. Smem tiles XOR-swizzled (f4 ^ (row&7)) -> conflict-free.
// ---------------------------------------------------------------------------
__global__ __launch_bounds__(256, 2) void proj_kernel(const float* __restrict__ q) {
    extern __shared__ __align__(16) unsigned char smem_raw[];
    ulonglong2* As = (ulonglong2*)smem_raw;   // [64][16] f4
    ulonglong2* Bs = As + 64 * 16;            // [128][16] f4

    int tid = threadIdx.x, w = tid >> 5, l = tid & 31;
    int r0 = blockIdx.x * 64;
    const float4* qf4 = (const float4*)q;        // row stride 256 f4
    const float4* wf4 = (const float4*)g_WeffT;  // row stride 256 f4

    unsigned long long acc[8][4];
    #pragma unroll
    for (int i = 0; i < 8; ++i)
        #pragma unroll
        for (int jj = 0; jj < 4; ++jj) acc[i][jj] = 0ull;

    for (int kc = 0; kc < 16; ++kc) {
        __syncthreads();
        #pragma unroll
        for (int it = 0; it < 4; ++it) {            // A tile: 64x16 f4
            int idx = tid + it * 256;
            int r = idx >> 4, g = idx & 15;
            ((float4*)As)[r * 16 + (g ^ (r & 7))] = qf4[(size_t)(r0 + r) * 256 + kc * 16 + g];
        }
        #pragma unroll
        for (int it = 0; it < 8; ++it) {            // B tile: 128x16 f4
            int idx = tid + it * 256;
            int r = idx >> 4, g = idx & 15;
            ((float4*)Bs)[r * 16 + (g ^ (r & 7))] = wf4[(size_t)r * 256 + kc * 16 + g];
        }
        __syncthreads();

        #pragma unroll 4
        for (int g4 = 0; g4 < 16; ++g4) {
            ulonglong2 bv[4];
            #pragma unroll
            for (int jj = 0; jj < 4; ++jj) {
                int r = l + 32 * jj;
                bv[jj] = Bs[r * 16 + (g4 ^ (r & 7))];
            }
            #pragma unroll
            for (int i = 0; i < 8; ++i) {
                int r = w * 8 + i;
                ulonglong2 av = As[r * 16 + (g4 ^ (r & 7))];
                #pragma unroll
                for (int jj = 0; jj < 4; ++jj) {
                    fma2(acc[i][jj], av.x, bv[jj].x);
                    fma2(acc[i][jj], av.y, bv[jj].y);
                }
            }
        }
    }

    float be[4];
    #pragma unroll
    for (int jj = 0; jj < 4; ++jj) be[jj] = g_beff[l + 32 * jj];
    #pragma unroll
    for (int i = 0; i < 8; ++i) {
        int row = r0 + w * 8 + i;
        float ns = 0.f;
        #pragma unroll
        for (int jj = 0; jj < 4; ++jj) {
            float y = lo32(acc[i][jj]) + hi32(acc[i][jj]) + be[jj];
            g_y[(size_t)row * HP + l + 32 * jj] = y;
            ns += y * y;   // padded cols are exactly 0 -> sum over 128 == over 120
        }
        #pragma unroll
        for (int off = 16; off; off >>= 1) ns += __shfl_xor_sync(0xffffffffu, ns, off);
        if (l == 0) g_norm[row] = ns;
    }
}

// ---------------------------------------------------------------------------
// Kernel 3: per 64-row block: S = y_r @ y_c^T (K=128), score = exp2(cA*dist),
// unnorm = exp2(score*log2e) stored to out; rowsum accumulated in regs.
// grid 256 = 8 batches x 32 row-tiles; each CTA sweeps all 2048 cols.
// ---------------------------------------------------------------------------
__global__ __launch_bounds__(256, 2) void score_kernel(const float* __restrict__ pid,
                                                       float* __restrict__ out) {
    extern __shared__ __align__(16) unsigned char smem_raw[];
    ulonglong2* yRs = (ulonglong2*)smem_raw;  // [64][32] f4
    ulonglong2* yCs = yRs + 64 * 32;          // [128][32] f4
    __shared__ float nR[64], nC[128];

    int tid = threadIdx.x, w = tid >> 5, l = tid & 31;
    int b  = blockIdx.x >> 5;
    int i0 = (blockIdx.x & 31) * 64;
    const float4* yb4 = (const float4*)(g_y + (size_t)b * LL * HP);  // row = 32 f4
    float p  = pid[0];
    float cA = -0.5f * p * p * LOG2E;

    #pragma unroll
    for (int it = 0; it < 8; ++it) {          // row block 64x32 f4
        int idx = tid + it * 256;
        int r = idx >> 5, g = idx & 31;
        ((float4*)yRs)[r * 32 + (g ^ (r & 7))] = yb4[(size_t)(i0 + r) * 32 + g];
    }
    if (tid < 64) nR[tid] = g_norm[b * LL + i0 + tid];

    float rsum[8];
    #pragma unroll
    for (int i = 0; i < 8; ++i) rsum[i] = 0.f;

    for (int j0 = 0; j0 < LL; j0 += 128) {
        __syncthreads();
        #pragma unroll
        for (int it = 0; it < 16; ++it) {     // col block 128x32 f4
            int idx = tid + it * 256;
            int r = idx >> 5, g = idx & 31;
            ((float4*)yCs)[r * 32 + (g ^ (r & 7))] = yb4[(size_t)(j0 + r) * 32 + g];
        }
        if (tid < 128) nC[tid] = g_norm[b * LL + j0 + tid];
        __syncthreads();

        unsigned long long acc[8][4];
        #pragma unroll
        for (int i = 0; i < 8; ++i)
            #pragma unroll
            for (int jj = 0; jj < 4; ++jj) acc[i][jj] = 0ull;

        #pragma unroll 8
        for (int g4 = 0; g4 < 32; ++g4) {
            ulonglong2 bv[4];
            #pragma unroll
            for (int jj = 0; jj < 4; ++jj) {
                int r = l + 32 * jj;
                bv[jj] = yCs[r * 32 + (g4 ^ (r & 7))];
            }
            #pragma unroll
            for (int i = 0; i < 8; ++i) {
                int r = w * 8 + i;
                ulonglong2 av = yRs[r * 32 + (g4 ^ (r & 7))];
                #pragma unroll
                for (int jj = 0; jj < 4; ++jj) {
                    fma2(acc[i][jj], av.x, bv[jj].x);
                    fma2(acc[i][jj], av.y, bv[jj].y);
                }
            }
        }

        float nCv[4];
        #pragma unroll
        for (int jj = 0; jj < 4; ++jj) nCv[jj] = nC[l + 32 * jj];
        #pragma unroll
        for (int i = 0; i < 8; ++i) {
            float ni = nR[w * 8 + i];
            float* orow = out + (size_t)(b * LL + i0 + w * 8 + i) * LL + j0;
            #pragma unroll
            for (int jj = 0; jj < 4; ++jj) {
                float dot  = lo32(acc[i][jj]) + hi32(acc[i][jj]);
                float dist = fmaf(-2.f, dot, ni + nCv[jj]);
                float s = ex2(cA * dist);        // exp(-0.5*scale*dist)
                float e = ex2(s * LOG2E);        // exp(score) — no max needed, s in (0,1]
                rsum[i] += e;
                orow[l + 32 * jj] = e;
            }
        }
    }

    #pragma unroll
    for (int i = 0; i < 8; ++i) {
        float v = rsum[i];
        #pragma unroll
        for (int off = 16; off; off >>= 1) v += __shfl_xor_sync(0xffffffffu, v, off);
        if (l == 0) g_rowsum[b * LL + i0 + w * 8 + i] = v;
    }
}

// ---------------------------------------------------------------------------
// Kernel 4: out *= 1/rowsum  (float4 grid, 512 f4 per row)
// ---------------------------------------------------------------------------
__global__ void norm_kernel(float* __restrict__ out) {
    int gid = blockIdx.x * blockDim.x + threadIdx.x;   // 8388608 f4 total
    float4* o4 = (float4*)out;
    float rs = g_rowsum[gid >> 9];
    float inv; asm("rcp.approx.ftz.f32 %0, %1;" : "=f"(inv) : "f"(rs));
    float4 v = o4[gid];
    v.x *= inv; v.y *= inv; v.z *= inv; v.w *= inv;
    o4[gid] = v;
}

extern "C" void kernel_launch(void* const* d_in, const int* in_sizes, int n_in,
                              void* d_out, int out_size) {
    const float* q   = (const float*)d_in[0];
    // d_in[1] = key: unused by the reference module
    const float* qw  = (const float*)d_in[2];
    const float* qb  = (const float*)d_in[3];
    const float* W   = (const float*)d_in[4];
    const float* pid = (const float*)d_in[5];
    float* out = (float*)d_out;

    cudaFuncSetAttribute(proj_kernel,  cudaFuncAttributeMaxDynamicSharedMemorySize, 49152);
    cudaFuncSetAttribute(score_kernel, cudaFuncAttributeMaxDynamicSharedMemorySize, 98304);

    prep_kernel<<<128, 256>>>(qw, qb, W);
    proj_kernel<<<256, 256, 49152>>>(q);
    score_kernel<<<256, 256, 98304>>>(pid, out);
    norm_kernel<<<(BB * LL * LL / 4) / 256, 256>>>(out);
}

// round 5
// speedup vs baseline: 1.2690x; 1.2690x over previous
#include <cuda_runtime.h>
#include <cuda_fp16.h>
#include <cstdint>

#define BB 8
#define LL 2048
#define DD 1024
#define HH 120
#define HP 128
#define SK 256   // stored split: [hi(128) | lo(128)] fp16
#define LOG2E 1.44269504088896340736f

// Scratch (device globals; no allocs allowed)
__device__ float g_WeffT[HP * DD];                              // [128][1024]
__device__ float g_beff[HP];
__device__ __align__(256) __half g_y2[(size_t)BB * LL * SK];    // [16384][256] hi|lo
__device__ float g_norm[BB * LL];

// ---------------- PTX helpers ----------------
static __device__ __forceinline__ void fma2(unsigned long long &c,
                                            unsigned long long a,
                                            unsigned long long b) {
    asm("fma.rn.f32x2 %0, %1, %2, %0;" : "+l"(c) : "l"(a), "l"(b));
}
static __device__ __forceinline__ float ex2(float x) {
    float r; asm("ex2.approx.ftz.f32 %0, %1;" : "=f"(r) : "f"(x)); return r;
}
static __device__ __forceinline__ float lo32(unsigned long long v) {
    return __uint_as_float((unsigned)(v & 0xffffffffull));
}
static __device__ __forceinline__ float hi32(unsigned long long v) {
    return __uint_as_float((unsigned)(v >> 32));
}
static __device__ __forceinline__ uint32_t smem_u32(const void* p) {
    uint32_t a;
    asm("{ .reg .u64 t; cvta.to.shared.u64 t, %1; cvt.u32.u64 %0, t; }" : "=r"(a) : "l"(p));
    return a;
}
static __device__ __forceinline__ void cpa16(uint32_t s, const void* g) {
    asm volatile("cp.async.cg.shared.global [%0], [%1], 16;" :: "r"(s), "l"(g));
}
static __device__ __forceinline__ void cpa_commit() { asm volatile("cp.async.commit_group;" ::: "memory"); }
static __device__ __forceinline__ void cpa_wait0()  { asm volatile("cp.async.wait_group 0;" ::: "memory"); }
static __device__ __forceinline__ void ldsm4(uint32_t& r0, uint32_t& r1, uint32_t& r2, uint32_t& r3,
                                             uint32_t addr) {
    asm volatile("ldmatrix.sync.aligned.m8n8.x4.shared.b16 {%0,%1,%2,%3}, [%4];"
                 : "=r"(r0), "=r"(r1), "=r"(r2), "=r"(r3) : "r"(addr));
}
static __device__ __forceinline__ void mma16816(float* d, const uint32_t* a, const uint32_t* b) {
    asm volatile("mma.sync.aligned.m16n8k16.row.col.f32.f16.f16.f32 "
                 "{%0,%1,%2,%3}, {%4,%5,%6,%7}, {%8,%9}, {%0,%1,%2,%3};"
                 : "+f"(d[0]), "+f"(d[1]), "+f"(d[2]), "+f"(d[3])
                 : "r"(a[0]), "r"(a[1]), "r"(a[2]), "r"(a[3]), "r"(b[0]), "r"(b[1]));
}

// ---------------------------------------------------------------------------
// Kernel 1: WeffT[j][d] = sum_h qW[h][d] * W[h][j];  beff[j] = qb @ W
// ---------------------------------------------------------------------------
__global__ void prep_kernel(const float* __restrict__ qw,
                            const float* __restrict__ qb,
                            const float* __restrict__ W) {
    int j = blockIdx.x;
    int tid = threadIdx.x;
    __shared__ float sw[HH];
    if (j < HH && tid < HH) sw[tid] = W[tid * HH + j];
    __syncthreads();

    if (j >= HH) {
        #pragma unroll
        for (int it = 0; it < 4; ++it) g_WeffT[j * DD + tid + it * 256] = 0.f;
        if (tid == 0) g_beff[j] = 0.f;
        return;
    }
    #pragma unroll
    for (int it = 0; it < 4; ++it) {
        int d = tid + it * 256;
        float acc = 0.f;
        #pragma unroll 8
        for (int h = 0; h < HH; ++h) acc += qw[h * DD + d] * sw[h];
        g_WeffT[j * DD + d] = acc;
    }
    if (tid == 0) {
        float acc = 0.f;
        for (int h = 0; h < HH; ++h) acc += qb[h] * sw[h];
        g_beff[j] = acc;
    }
}

// ---------------------------------------------------------------------------
// Kernel 2: y = q @ WeffT^T + beff; writes fp16 hi/lo split + fp32 row norms.
// ---------------------------------------------------------------------------
__global__ __launch_bounds__(256, 2) void proj_kernel(const float* __restrict__ q) {
    extern __shared__ __align__(16) unsigned char smem_raw[];
    ulonglong2* As = (ulonglong2*)smem_raw;   // [64][16] f4
    ulonglong2* Bs = As + 64 * 16;            // [128][16] f4

    int tid = threadIdx.x, w = tid >> 5, l = tid & 31;
    int r0 = blockIdx.x * 64;
    const float4* qf4 = (const float4*)q;
    const float4* wf4 = (const float4*)g_WeffT;

    unsigned long long acc[8][4];
    #pragma unroll
    for (int i = 0; i < 8; ++i)
        #pragma unroll
        for (int jj = 0; jj < 4; ++jj) acc[i][jj] = 0ull;

    for (int kc = 0; kc < 16; ++kc) {
        __syncthreads();
        #pragma unroll
        for (int it = 0; it < 4; ++it) {
            int idx = tid + it * 256;
            int r = idx >> 4, g = idx & 15;
            ((float4*)As)[r * 16 + (g ^ (r & 7))] = qf4[(size_t)(r0 + r) * 256 + kc * 16 + g];
        }
        #pragma unroll
        for (int it = 0; it < 8; ++it) {
            int idx = tid + it * 256;
            int r = idx >> 4, g = idx & 15;
            ((float4*)Bs)[r * 16 + (g ^ (r & 7))] = wf4[(size_t)r * 256 + kc * 16 + g];
        }
        __syncthreads();

        #pragma unroll 4
        for (int g4 = 0; g4 < 16; ++g4) {
            ulonglong2 bv[4];
            #pragma unroll
            for (int jj = 0; jj < 4; ++jj) {
                int r = l + 32 * jj;
                bv[jj] = Bs[r * 16 + (g4 ^ (r & 7))];
            }
            #pragma unroll
            for (int i = 0; i < 8; ++i) {
                int r = w * 8 + i;
                ulonglong2 av = As[r * 16 + (g4 ^ (r & 7))];
                #pragma unroll
                for (int jj = 0; jj < 4; ++jj) {
                    fma2(acc[i][jj], av.x, bv[jj].x);
                    fma2(acc[i][jj], av.y, bv[jj].y);
                }
            }
        }
    }

    float be[4];
    #pragma unroll
    for (int jj = 0; jj < 4; ++jj) be[jj] = g_beff[l + 32 * jj];
    #pragma unroll
    for (int i = 0; i < 8; ++i) {
        int row = r0 + w * 8 + i;
        float ns = 0.f;
        #pragma unroll
        for (int jj = 0; jj < 4; ++jj) {
            int col = l + 32 * jj;
            float y = lo32(acc[i][jj]) + hi32(acc[i][jj]) + be[jj];
            __half hi = __float2half_rn(y);
            float lof = y - __half2float(hi);
            g_y2[(size_t)row * SK + col]      = hi;
            g_y2[(size_t)row * SK + HP + col] = __float2half_rn(lof);
            ns += y * y;
        }
        #pragma unroll
        for (int off = 16; off; off >>= 1) ns += __shfl_xor_sync(0xffffffffu, ns, off);
        if (l == 0) g_norm[row] = ns;
    }
}

// ---------------------------------------------------------------------------
// Kernel 3 (mma.sync f16): per CTA 128 rows x all 2048 cols (16 tiles of 128).
// dot = hi.hi + lo.hi + hi.lo via 24 k-steps over the same [hi|lo] tiles
// (only lo.lo dropped: ~1e-7 rel). Fused exp epilogue + rowsum + rescale.
// ---------------------------------------------------------------------------
static __device__ __forceinline__ void load_tile(uint32_t sbase, const char* g0, int tid) {
    #pragma unroll
    for (int it = 0; it < 16; ++it) {
        int idx = tid + it * 256;           // 4096 16B-chunks
        int r = idx >> 5;                   // row 0..127
        int c = idx & 31;                   // chunk in row
        cpa16(sbase + r * 512 + ((c ^ (r & 7)) << 4), g0 + (size_t)r * 512 + (size_t)c * 16);
    }
}

__global__ __launch_bounds__(256, 1) void score_kernel(const float* __restrict__ pid,
                                                       float* __restrict__ out) {
    extern __shared__ unsigned char dsm[];
    __shared__ float s_cn[LL];    // cA * norm for the whole batch
    __shared__ float s_rs[128];   // rowsums

    const int tid = threadIdx.x, w = tid >> 5, l = tid & 31;
    const int b    = blockIdx.x >> 4;
    const int tile = blockIdx.x & 15;
    const int rb   = tile * 128;            // row base within batch
    const int wm = w & 1, wn = w >> 1;

    uint32_t abase = (smem_u32(dsm) + 1023) & ~1023u;
    uint32_t bbuf[2] = { abase + 65536u, abase + 131072u };

    const char* Yrow = (const char*)(g_y2 + (size_t)(b * LL + rb) * SK);
    const char* Ybat = (const char*)(g_y2 + (size_t)b * LL * SK);

    load_tile(abase, Yrow, tid);
    load_tile(bbuf[0], Ybat, tid);
    cpa_commit();

    const float p  = pid[0];
    const float cA = -0.5f * p * p * LOG2E;
    const float a2 = -2.f * cA;
    #pragma unroll
    for (int i = 0; i < 8; ++i) s_cn[tid + i * 256] = cA * g_norm[b * LL + tid + i * 256];
    if (tid < 128) s_rs[tid] = 0.f;

    // ldmatrix address precompute
    const int g = l >> 3;
    uint32_t aAddr[4], aSwz[4];
    #pragma unroll
    for (int mf = 0; mf < 4; ++mf) {
        int row = wm * 64 + mf * 16 + (l & 7) + ((g & 1) * 8);
        aAddr[mf] = abase + row * 512;
        aSwz[mf]  = row & 7;
    }
    const uint32_t ghA = (uint32_t)(g >> 1);
    uint32_t bRow[2], bSwz[2];
    #pragma unroll
    for (int nf2 = 0; nf2 < 2; ++nf2) {
        int row = wn * 32 + nf2 * 16 + (l & 7) + ((g >> 1) * 8);
        bRow[nf2] = (uint32_t)row * 512;
        bSwz[nf2] = row & 7;
    }
    const uint32_t ghB = (uint32_t)(g & 1);

    cpa_wait0();
    __syncthreads();

    // per-thread row constants (after barrier: s_cn fully populated)
    float cni[4][2];
    #pragma unroll
    for (int mf = 0; mf < 4; ++mf) {
        int r0l = wm * 64 + mf * 16 + (l >> 2);
        cni[mf][0] = s_cn[rb + r0l];
        cni[mf][1] = s_cn[rb + r0l + 8];
    }

    float part[8];
    #pragma unroll
    for (int i = 0; i < 8; ++i) part[i] = 0.f;

    #pragma unroll 1
    for (int t = 0; t < 16; ++t) {
        if (t < 15) {
            load_tile(bbuf[(t + 1) & 1], Ybat + (size_t)(t + 1) * 128 * 512, tid);
            cpa_commit();
        }

        float acc[4][4][4];
        #pragma unroll
        for (int mf = 0; mf < 4; ++mf)
            #pragma unroll
            for (int nf = 0; nf < 4; ++nf)
                #pragma unroll
                for (int k = 0; k < 4; ++k) acc[mf][nf][k] = 0.f;

        const uint32_t bb = bbuf[t & 1];
        // 24 k-steps: s<8: hi.hi; 8<=s<16: A=lo,B=hi; s>=16: A=hi,B=lo
        #pragma unroll
        for (int s = 0; s < 24; ++s) {
            const uint32_t kA = (s < 16) ? (uint32_t)s : (uint32_t)(s - 16);
            const uint32_t kB = (s < 8)  ? (uint32_t)s : (uint32_t)(s - 8);
            uint32_t a[4][4], bfr[2][4];
            #pragma unroll
            for (int mf = 0; mf < 4; ++mf)
                ldsm4(a[mf][0], a[mf][1], a[mf][2], a[mf][3],
                      aAddr[mf] + (((kA * 2 + ghA) ^ aSwz[mf]) << 4));
            #pragma unroll
            for (int nf2 = 0; nf2 < 2; ++nf2)
                ldsm4(bfr[nf2][0], bfr[nf2][1], bfr[nf2][2], bfr[nf2][3],
                      bb + bRow[nf2] + (((kB * 2 + ghB) ^ bSwz[nf2]) << 4));
            #pragma unroll
            for (int mf = 0; mf < 4; ++mf) {
                mma16816(acc[mf][0], a[mf], &bfr[0][0]);
                mma16816(acc[mf][1], a[mf], &bfr[0][2]);
                mma16816(acc[mf][2], a[mf], &bfr[1][0]);
                mma16816(acc[mf][3], a[mf], &bfr[1][2]);
            }
        }

        // epilogue: exp in exponent domain, store, rowsum partials
        #pragma unroll
        for (int nf = 0; nf < 4; ++nf) {
            int cl = wn * 32 + nf * 8 + (l & 3) * 2;
            float cnj0 = s_cn[t * 128 + cl];
            float cnj1 = s_cn[t * 128 + cl + 1];
            #pragma unroll
            for (int mf = 0; mf < 4; ++mf) {
                int r0l = wm * 64 + mf * 16 + (l >> 2);
                float e00 = ex2(LOG2E * ex2(fmaf(a2, acc[mf][nf][0], cni[mf][0] + cnj0)));
                float e01 = ex2(LOG2E * ex2(fmaf(a2, acc[mf][nf][1], cni[mf][0] + cnj1)));
                float e10 = ex2(LOG2E * ex2(fmaf(a2, acc[mf][nf][2], cni[mf][1] + cnj0)));
                float e11 = ex2(LOG2E * ex2(fmaf(a2, acc[mf][nf][3], cni[mf][1] + cnj1)));
                part[mf * 2]     += e00 + e01;
                part[mf * 2 + 1] += e10 + e11;
                float* o0 = out + (size_t)(b * LL + rb + r0l) * LL + t * 128 + cl;
                *(float2*)o0              = make_float2(e00, e01);
                *(float2*)(o0 + 8 * LL)   = make_float2(e10, e11);
            }
        }

        if (t < 15) {
            cpa_wait0();
            __syncthreads();
        }
    }

    // rowsum reduce: lanes 0..3 within each quad share rows
    #pragma unroll
    for (int i = 0; i < 8; ++i) {
        float v = part[i];
        v += __shfl_xor_sync(0xffffffffu, v, 1);
        v += __shfl_xor_sync(0xffffffffu, v, 2);
        if ((l & 3) == 0) {
            int r0l = wm * 64 + (i >> 1) * 16 + (l >> 2) + (i & 1) * 8;
            atomicAdd(&s_rs[r0l], v);
        }
    }
    __syncthreads();

    // fused normalize: each thread rescales half a row (1024 floats)
    {
        int row = tid >> 1;
        float inv; asm("rcp.approx.ftz.f32 %0, %1;" : "=f"(inv) : "f"(s_rs[row]));
        float4* o4 = (float4*)(out + (size_t)(b * LL + rb + row) * LL + (tid & 1) * 1024);
        #pragma unroll 8
        for (int i = 0; i < 256; ++i) {
            float4 v = o4[i];
            v.x *= inv; v.y *= inv; v.z *= inv; v.w *= inv;
            o4[i] = v;
        }
    }
}

extern "C" void kernel_launch(void* const* d_in, const int* in_sizes, int n_in,
                              void* d_out, int out_size) {
    const float* q   = (const float*)d_in[0];
    const float* qw  = (const float*)d_in[2];
    const float* qb  = (const float*)d_in[3];
    const float* W   = (const float*)d_in[4];
    const float* pid = (const float*)d_in[5];
    float* out = (float*)d_out;

    cudaFuncSetAttribute(proj_kernel,  cudaFuncAttributeMaxDynamicSharedMemorySize, 49152);
    cudaFuncSetAttribute(score_kernel, cudaFuncAttributeMaxDynamicSharedMemorySize, 197632);

    prep_kernel<<<128, 256>>>(qw, qb, W);
    proj_kernel<<<256, 256, 49152>>>(q);
    score_kernel<<<128, 256, 197632>>>(pid, out);
}

// round 6
// speedup vs baseline: 1.2704x; 1.0011x over previous
#include <cuda_runtime.h>
#include <cuda_fp16.h>
#include <cstdint>

#define BB 8
#define LL 2048
#define DD 1024
#define HH 120
#define HP 128
#define SK 256   // stored split: [hi(128) | lo(128)] fp16
#define LOG2E 1.44269504088896340736f

// Scratch (device globals; no allocs allowed)
__device__ float g_WeffT[HP * DD];                              // [128][1024]
__device__ float g_beff[HP];
__device__ __align__(256) __half g_y2[(size_t)BB * LL * SK];    // [16384][256] hi|lo
__device__ float g_norm[BB * LL];

// ---------------- PTX helpers ----------------
static __device__ __forceinline__ void fma2(unsigned long long &c,
                                            unsigned long long a,
                                            unsigned long long b) {
    asm("fma.rn.f32x2 %0, %1, %2, %0;" : "+l"(c) : "l"(a), "l"(b));
}
static __device__ __forceinline__ float ex2(float x) {
    float r; asm("ex2.approx.ftz.f32 %0, %1;" : "=f"(r) : "f"(x)); return r;
}
static __device__ __forceinline__ float lo32(unsigned long long v) {
    return __uint_as_float((unsigned)(v & 0xffffffffull));
}
static __device__ __forceinline__ float hi32(unsigned long long v) {
    return __uint_as_float((unsigned)(v >> 32));
}
static __device__ __forceinline__ uint32_t smem_u32(const void* p) {
    uint32_t a;
    asm("{ .reg .u64 t; cvta.to.shared.u64 t, %1; cvt.u32.u64 %0, t; }" : "=r"(a) : "l"(p));
    return a;
}
static __device__ __forceinline__ void cpa16(uint32_t s, const void* g) {
    asm volatile("cp.async.cg.shared.global [%0], [%1], 16;" :: "r"(s), "l"(g));
}
static __device__ __forceinline__ void cpa_commit() { asm volatile("cp.async.commit_group;" ::: "memory"); }
static __device__ __forceinline__ void cpa_wait0()  { asm volatile("cp.async.wait_group 0;" ::: "memory"); }
static __device__ __forceinline__ void ldsm4(uint32_t& r0, uint32_t& r1, uint32_t& r2, uint32_t& r3,
                                             uint32_t addr) {
    asm volatile("ldmatrix.sync.aligned.m8n8.x4.shared.b16 {%0,%1,%2,%3}, [%4];"
                 : "=r"(r0), "=r"(r1), "=r"(r2), "=r"(r3) : "r"(addr));
}
static __device__ __forceinline__ void mma16816(float* d, const uint32_t* a, const uint32_t* b) {
    asm volatile("mma.sync.aligned.m16n8k16.row.col.f32.f16.f16.f32 "
                 "{%0,%1,%2,%3}, {%4,%5,%6,%7}, {%8,%9}, {%0,%1,%2,%3};"
                 : "+f"(d[0]), "+f"(d[1]), "+f"(d[2]), "+f"(d[3])
                 : "r"(a[0]), "r"(a[1]), "r"(a[2]), "r"(a[3]), "r"(b[0]), "r"(b[1]));
}

// ---------------------------------------------------------------------------
// Kernel 1: WeffT[j][d] = sum_h qW[h][d] * W[h][j];  beff[j] = qb @ W
// ---------------------------------------------------------------------------
__global__ void prep_kernel(const float* __restrict__ qw,
                            const float* __restrict__ qb,
                            const float* __restrict__ W) {
    int j = blockIdx.x;
    int tid = threadIdx.x;
    __shared__ float sw[HH];
    if (j < HH && tid < HH) sw[tid] = W[tid * HH + j];
    __syncthreads();

    if (j >= HH) {
        #pragma unroll
        for (int it = 0; it < 4; ++it) g_WeffT[j * DD + tid + it * 256] = 0.f;
        if (tid == 0) g_beff[j] = 0.f;
        return;
    }
    #pragma unroll
    for (int it = 0; it < 4; ++it) {
        int d = tid + it * 256;
        float acc = 0.f;
        #pragma unroll 8
        for (int h = 0; h < HH; ++h) acc += qw[h * DD + d] * sw[h];
        g_WeffT[j * DD + d] = acc;
    }
    if (tid == 0) {
        float acc = 0.f;
        for (int h = 0; h < HH; ++h) acc += qb[h] * sw[h];
        g_beff[j] = acc;
    }
}

// ---------------------------------------------------------------------------
// Kernel 2: y = q @ WeffT^T + beff; writes fp16 hi/lo split + fp32 row norms.
// ---------------------------------------------------------------------------
__global__ __launch_bounds__(256, 2) void proj_kernel(const float* __restrict__ q) {
    extern __shared__ __align__(16) unsigned char smem_raw[];
    ulonglong2* As = (ulonglong2*)smem_raw;   // [64][16] f4
    ulonglong2* Bs = As + 64 * 16;            // [128][16] f4

    int tid = threadIdx.x, w = tid >> 5, l = tid & 31;
    int r0 = blockIdx.x * 64;
    const float4* qf4 = (const float4*)q;
    const float4* wf4 = (const float4*)g_WeffT;

    unsigned long long acc[8][4];
    #pragma unroll
    for (int i = 0; i < 8; ++i)
        #pragma unroll
        for (int jj = 0; jj < 4; ++jj) acc[i][jj] = 0ull;

    for (int kc = 0; kc < 16; ++kc) {
        __syncthreads();
        #pragma unroll
        for (int it = 0; it < 4; ++it) {
            int idx = tid + it * 256;
            int r = idx >> 4, g = idx & 15;
            ((float4*)As)[r * 16 + (g ^ (r & 7))] = qf4[(size_t)(r0 + r) * 256 + kc * 16 + g];
        }
        #pragma unroll
        for (int it = 0; it < 8; ++it) {
            int idx = tid + it * 256;
            int r = idx >> 4, g = idx & 15;
            ((float4*)Bs)[r * 16 + (g ^ (r & 7))] = wf4[(size_t)r * 256 + kc * 16 + g];
        }
        __syncthreads();

        #pragma unroll 4
        for (int g4 = 0; g4 < 16; ++g4) {
            ulonglong2 bv[4];
            #pragma unroll
            for (int jj = 0; jj < 4; ++jj) {
                int r = l + 32 * jj;
                bv[jj] = Bs[r * 16 + (g4 ^ (r & 7))];
            }
            #pragma unroll
            for (int i = 0; i < 8; ++i) {
                int r = w * 8 + i;
                ulonglong2 av = As[r * 16 + (g4 ^ (r & 7))];
                #pragma unroll
                for (int jj = 0; jj < 4; ++jj) {
                    fma2(acc[i][jj], av.x, bv[jj].x);
                    fma2(acc[i][jj], av.y, bv[jj].y);
                }
            }
        }
    }

    float be[4];
    #pragma unroll
    for (int jj = 0; jj < 4; ++jj) be[jj] = g_beff[l + 32 * jj];
    #pragma unroll
    for (int i = 0; i < 8; ++i) {
        int row = r0 + w * 8 + i;
        float ns = 0.f;
        #pragma unroll
        for (int jj = 0; jj < 4; ++jj) {
            int col = l + 32 * jj;
            float y = lo32(acc[i][jj]) + hi32(acc[i][jj]) + be[jj];
            __half hi = __float2half_rn(y);
            float lof = y - __half2float(hi);
            g_y2[(size_t)row * SK + col]      = hi;
            g_y2[(size_t)row * SK + HP + col] = __float2half_rn(lof);
            ns += y * y;
        }
        #pragma unroll
        for (int off = 16; off; off >>= 1) ns += __shfl_xor_sync(0xffffffffu, ns, off);
        if (l == 0) g_norm[row] = ns;
    }
}

// ---------------------------------------------------------------------------
// Kernel 3 (mma.sync f16): per CTA 128 rows x all 2048 cols (16 tiles of 128).
// dot = hi.hi + lo.hi + hi.lo via 24 k-steps over the same [hi|lo] tiles
// (only lo.lo dropped: ~1e-7 rel). Fused exp epilogue + rowsum + rescale.
// ---------------------------------------------------------------------------
static __device__ __forceinline__ void load_tile(uint32_t sbase, const char* g0, int tid) {
    #pragma unroll
    for (int it = 0; it < 16; ++it) {
        int idx = tid + it * 256;           // 4096 16B-chunks
        int r = idx >> 5;                   // row 0..127
        int c = idx & 31;                   // chunk in row
        cpa16(sbase + r * 512 + ((c ^ (r & 7)) << 4), g0 + (size_t)r * 512 + (size_t)c * 16);
    }
}

__global__ __launch_bounds__(256, 1) void score_kernel(const float* __restrict__ pid,
                                                       float* __restrict__ out) {
    extern __shared__ unsigned char dsm[];
    __shared__ float s_cn[LL];    // cA * norm for the whole batch
    __shared__ float s_rs[128];   // rowsums

    const int tid = threadIdx.x, w = tid >> 5, l = tid & 31;
    const int b    = blockIdx.x >> 4;
    const int tile = blockIdx.x & 15;
    const int rb   = tile * 128;            // row base within batch
    const int wm = w & 1, wn = w >> 1;

    uint32_t abase = (smem_u32(dsm) + 1023) & ~1023u;
    uint32_t bbuf[2] = { abase + 65536u, abase + 131072u };

    const char* Yrow = (const char*)(g_y2 + (size_t)(b * LL + rb) * SK);
    const char* Ybat = (const char*)(g_y2 + (size_t)b * LL * SK);

    load_tile(abase, Yrow, tid);
    load_tile(bbuf[0], Ybat, tid);
    cpa_commit();

    const float p  = pid[0];
    const float cA = -0.5f * p * p * LOG2E;
    const float a2 = -2.f * cA;
    #pragma unroll
    for (int i = 0; i < 8; ++i) s_cn[tid + i * 256] = cA * g_norm[b * LL + tid + i * 256];
    if (tid < 128) s_rs[tid] = 0.f;

    // ldmatrix address precompute
    const int g = l >> 3;
    uint32_t aAddr[4], aSwz[4];
    #pragma unroll
    for (int mf = 0; mf < 4; ++mf) {
        int row = wm * 64 + mf * 16 + (l & 7) + ((g & 1) * 8);
        aAddr[mf] = abase + row * 512;
        aSwz[mf]  = row & 7;
    }
    const uint32_t ghA = (uint32_t)(g >> 1);
    uint32_t bRow[2], bSwz[2];
    #pragma unroll
    for (int nf2 = 0; nf2 < 2; ++nf2) {
        int row = wn * 32 + nf2 * 16 + (l & 7) + ((g >> 1) * 8);
        bRow[nf2] = (uint32_t)row * 512;
        bSwz[nf2] = row & 7;
    }
    const uint32_t ghB = (uint32_t)(g & 1);

    cpa_wait0();
    __syncthreads();

    // per-thread row constants (after barrier: s_cn fully populated)
    float cni[4][2];
    #pragma unroll
    for (int mf = 0; mf < 4; ++mf) {
        int r0l = wm * 64 + mf * 16 + (l >> 2);
        cni[mf][0] = s_cn[rb + r0l];
        cni[mf][1] = s_cn[rb + r0l + 8];
    }

    float part[8];
    #pragma unroll
    for (int i = 0; i < 8; ++i) part[i] = 0.f;

    #pragma unroll 1
    for (int t = 0; t < 16; ++t) {
        if (t < 15) {
            load_tile(bbuf[(t + 1) & 1], Ybat + (size_t)(t + 1) * 128 * 512, tid);
            cpa_commit();
        }

        float acc[4][4][4];
        #pragma unroll
        for (int mf = 0; mf < 4; ++mf)
            #pragma unroll
            for (int nf = 0; nf < 4; ++nf)
                #pragma unroll
                for (int k = 0; k < 4; ++k) acc[mf][nf][k] = 0.f;

        const uint32_t bb = bbuf[t & 1];
        // 24 k-steps: s<8: hi.hi; 8<=s<16: A=lo,B=hi; s>=16: A=hi,B=lo
        #pragma unroll
        for (int s = 0; s < 24; ++s) {
            const uint32_t kA = (s < 16) ? (uint32_t)s : (uint32_t)(s - 16);
            const uint32_t kB = (s < 8)  ? (uint32_t)s : (uint32_t)(s - 8);
            uint32_t a[4][4], bfr[2][4];
            #pragma unroll
            for (int mf = 0; mf < 4; ++mf)
                ldsm4(a[mf][0], a[mf][1], a[mf][2], a[mf][3],
                      aAddr[mf] + (((kA * 2 + ghA) ^ aSwz[mf]) << 4));
            #pragma unroll
            for (int nf2 = 0; nf2 < 2; ++nf2)
                ldsm4(bfr[nf2][0], bfr[nf2][1], bfr[nf2][2], bfr[nf2][3],
                      bb + bRow[nf2] + (((kB * 2 + ghB) ^ bSwz[nf2]) << 4));
            #pragma unroll
            for (int mf = 0; mf < 4; ++mf) {
                mma16816(acc[mf][0], a[mf], &bfr[0][0]);
                mma16816(acc[mf][1], a[mf], &bfr[0][2]);
                mma16816(acc[mf][2], a[mf], &bfr[1][0]);
                mma16816(acc[mf][3], a[mf], &bfr[1][2]);
            }
        }

        // epilogue: exp in exponent domain, store, rowsum partials
        #pragma unroll
        for (int nf = 0; nf < 4; ++nf) {
            int cl = wn * 32 + nf * 8 + (l & 3) * 2;
            float cnj0 = s_cn[t * 128 + cl];
            float cnj1 = s_cn[t * 128 + cl + 1];
            #pragma unroll
            for (int mf = 0; mf < 4; ++mf) {
                int r0l = wm * 64 + mf * 16 + (l >> 2);
                float e00 = ex2(LOG2E * ex2(fmaf(a2, acc[mf][nf][0], cni[mf][0] + cnj0)));
                float e01 = ex2(LOG2E * ex2(fmaf(a2, acc[mf][nf][1], cni[mf][0] + cnj1)));
                float e10 = ex2(LOG2E * ex2(fmaf(a2, acc[mf][nf][2], cni[mf][1] + cnj0)));
                float e11 = ex2(LOG2E * ex2(fmaf(a2, acc[mf][nf][3], cni[mf][1] + cnj1)));
                part[mf * 2]     += e00 + e01;
                part[mf * 2 + 1] += e10 + e11;
                float* o0 = out + (size_t)(b * LL + rb + r0l) * LL + t * 128 + cl;
                *(float2*)o0              = make_float2(e00, e01);
                *(float2*)(o0 + 8 * LL)   = make_float2(e10, e11);
            }
        }

        if (t < 15) {
            cpa_wait0();
            __syncthreads();
        }
    }

    // rowsum reduce: lanes 0..3 within each quad share rows
    #pragma unroll
    for (int i = 0; i < 8; ++i) {
        float v = part[i];
        v += __shfl_xor_sync(0xffffffffu, v, 1);
        v += __shfl_xor_sync(0xffffffffu, v, 2);
        if ((l & 3) == 0) {
            int r0l = wm * 64 + (i >> 1) * 16 + (l >> 2) + (i & 1) * 8;
            atomicAdd(&s_rs[r0l], v);
        }
    }
    __syncthreads();

    // fused normalize: each thread rescales half a row (1024 floats)
    {
        int row = tid >> 1;
        float inv; asm("rcp.approx.ftz.f32 %0, %1;" : "=f"(inv) : "f"(s_rs[row]));
        float4* o4 = (float4*)(out + (size_t)(b * LL + rb + row) * LL + (tid & 1) * 1024);
        #pragma unroll 8
        for (int i = 0; i < 256; ++i) {
            float4 v = o4[i];
            v.x *= inv; v.y *= inv; v.z *= inv; v.w *= inv;
            o4[i] = v;
        }
    }
}

extern "C" void kernel_launch(void* const* d_in, const int* in_sizes, int n_in,
                              void* d_out, int out_size) {
    const float* q   = (const float*)d_in[0];
    const float* qw  = (const float*)d_in[2];
    const float* qb  = (const float*)d_in[3];
    const float* W   = (const float*)d_in[4];
    const float* pid = (const float*)d_in[5];
    float* out = (float*)d_out;

    cudaFuncSetAttribute(proj_kernel,  cudaFuncAttributeMaxDynamicSharedMemorySize, 49152);
    cudaFuncSetAttribute(score_kernel, cudaFuncAttributeMaxDynamicSharedMemorySize, 197632);

    prep_kernel<<<128, 256>>>(qw, qb, W);
    proj_kernel<<<256, 256, 49152>>>(q);
    score_kernel<<<128, 256, 197632>>>(pid, out);
}

// round 7
// speedup vs baseline: 1.7076x; 1.3441x over previous
#include <cuda_runtime.h>
#include <cuda_fp16.h>
#include <cstdint>

#define BB 8
#define LL 2048
#define DD 1024
#define HH 120
#define HP 128
#define SK 256   // stored split: [hi(128) | lo(128)] fp16
#define LOG2E 1.44269504088896340736f
#define LOG2LOG2E 0.5287663729448977f

// Scratch (device globals; no allocs allowed)
__device__ float g_WeffT[HP * DD];                              // [128][1024]
__device__ float g_beff[HP];
__device__ __align__(256) __half g_y2[(size_t)BB * LL * SK];    // [16384][256] hi|lo
__device__ float g_norm[BB * LL];

// ---------------- PTX helpers ----------------
static __device__ __forceinline__ void fma2(unsigned long long &c,
                                            unsigned long long a,
                                            unsigned long long b) {
    asm("fma.rn.f32x2 %0, %1, %2, %0;" : "+l"(c) : "l"(a), "l"(b));
}
static __device__ __forceinline__ float ex2(float x) {
    float r; asm("ex2.approx.ftz.f32 %0, %1;" : "=f"(r) : "f"(x)); return r;
}
static __device__ __forceinline__ float lo32(unsigned long long v) {
    return __uint_as_float((unsigned)(v & 0xffffffffull));
}
static __device__ __forceinline__ float hi32(unsigned long long v) {
    return __uint_as_float((unsigned)(v >> 32));
}
static __device__ __forceinline__ uint32_t smem_u32(const void* p) {
    uint32_t a;
    asm("{ .reg .u64 t; cvta.to.shared.u64 t, %1; cvt.u32.u64 %0, t; }" : "=r"(a) : "l"(p));
    return a;
}
static __device__ __forceinline__ void cpa16(uint32_t s, const void* g) {
    asm volatile("cp.async.cg.shared.global [%0], [%1], 16;" :: "r"(s), "l"(g));
}
static __device__ __forceinline__ void cpa_commit() { asm volatile("cp.async.commit_group;" ::: "memory"); }
static __device__ __forceinline__ void cpa_wait0()  { asm volatile("cp.async.wait_group 0;" ::: "memory"); }
static __device__ __forceinline__ void ldsm4(uint32_t& r0, uint32_t& r1, uint32_t& r2, uint32_t& r3,
                                             uint32_t addr) {
    asm volatile("ldmatrix.sync.aligned.m8n8.x4.shared.b16 {%0,%1,%2,%3}, [%4];"
                 : "=r"(r0), "=r"(r1), "=r"(r2), "=r"(r3) : "r"(addr));
}
static __device__ __forceinline__ void mma16816(float* d, const uint32_t* a, const uint32_t* b) {
    asm volatile("mma.sync.aligned.m16n8k16.row.col.f32.f16.f16.f32 "
                 "{%0,%1,%2,%3}, {%4,%5,%6,%7}, {%8,%9}, {%0,%1,%2,%3};"
                 : "+f"(d[0]), "+f"(d[1]), "+f"(d[2]), "+f"(d[3])
                 : "r"(a[0]), "r"(a[1]), "r"(a[2]), "r"(a[3]), "r"(b[0]), "r"(b[1]));
}

// ---------------------------------------------------------------------------
// Kernel 1: Weff^T[j][d] = sum_h qW[h][d] * W[h][j];  beff = qb @ W
// Smem-tiled: W (zero-padded to [120][128]) fully resident; 128 CTAs x 8 d-cols.
// ---------------------------------------------------------------------------
__global__ __launch_bounds__(256) void prep_kernel(const float* __restrict__ qw,
                                                   const float* __restrict__ qb,
                                                   const float* __restrict__ W) {
    extern __shared__ float ps[];          // Wp[120*128] + qs[120*8]
    float* Wp = ps;
    float* qs = ps + HH * HP;
    const int tid = threadIdx.x;
    const int d0 = blockIdx.x * 8;

    for (int i = tid; i < HH * HP; i += 256) {
        int j = i & 127;
        Wp[i] = (j < HH) ? W[(i >> 7) * HH + j] : 0.f;
    }
    for (int i = tid; i < HH * 8; i += 256)
        qs[i] = qw[(i >> 3) * DD + d0 + (i & 7)];
    __syncthreads();

    const int j = tid >> 1, dh = (tid & 1) * 4;
    float4 acc = make_float4(0.f, 0.f, 0.f, 0.f);
    #pragma unroll 8
    for (int h = 0; h < HH; ++h) {
        float wv = Wp[h * HP + j];
        float4 qv = *(const float4*)(qs + h * 8 + dh);
        acc.x += wv * qv.x; acc.y += wv * qv.y;
        acc.z += wv * qv.z; acc.w += wv * qv.w;
    }
    *(float4*)(g_WeffT + (size_t)j * DD + d0 + dh) = acc;

    if (blockIdx.x == 0 && tid < HP) {
        float a = 0.f;
        #pragma unroll 8
        for (int h = 0; h < HH; ++h) a += qb[h] * Wp[h * HP + tid];
        g_beff[tid] = a;
    }
}

// ---------------------------------------------------------------------------
// Kernel 2: y = q @ WeffT^T + beff; writes fp16 hi/lo split + fp32 row norms.
// ---------------------------------------------------------------------------
__global__ __launch_bounds__(256, 2) void proj_kernel(const float* __restrict__ q) {
    extern __shared__ __align__(16) unsigned char smem_raw[];
    ulonglong2* As = (ulonglong2*)smem_raw;   // [64][16] f4
    ulonglong2* Bs = As + 64 * 16;            // [128][16] f4

    int tid = threadIdx.x, w = tid >> 5, l = tid & 31;
    int r0 = blockIdx.x * 64;
    const float4* qf4 = (const float4*)q;
    const float4* wf4 = (const float4*)g_WeffT;

    unsigned long long acc[8][4];
    #pragma unroll
    for (int i = 0; i < 8; ++i)
        #pragma unroll
        for (int jj = 0; jj < 4; ++jj) acc[i][jj] = 0ull;

    for (int kc = 0; kc < 16; ++kc) {
        __syncthreads();
        #pragma unroll
        for (int it = 0; it < 4; ++it) {
            int idx = tid + it * 256;
            int r = idx >> 4, g = idx & 15;
            ((float4*)As)[r * 16 + (g ^ (r & 7))] = qf4[(size_t)(r0 + r) * 256 + kc * 16 + g];
        }
        #pragma unroll
        for (int it = 0; it < 8; ++it) {
            int idx = tid + it * 256;
            int r = idx >> 4, g = idx & 15;
            ((float4*)Bs)[r * 16 + (g ^ (r & 7))] = wf4[(size_t)r * 256 + kc * 16 + g];
        }
        __syncthreads();

        #pragma unroll 4
        for (int g4 = 0; g4 < 16; ++g4) {
            ulonglong2 bv[4];
            #pragma unroll
            for (int jj = 0; jj < 4; ++jj) {
                int r = l + 32 * jj;
                bv[jj] = Bs[r * 16 + (g4 ^ (r & 7))];
            }
            #pragma unroll
            for (int i = 0; i < 8; ++i) {
                int r = w * 8 + i;
                ulonglong2 av = As[r * 16 + (g4 ^ (r & 7))];
                #pragma unroll
                for (int jj = 0; jj < 4; ++jj) {
                    fma2(acc[i][jj], av.x, bv[jj].x);
                    fma2(acc[i][jj], av.y, bv[jj].y);
                }
            }
        }
    }

    float be[4];
    #pragma unroll
    for (int jj = 0; jj < 4; ++jj) be[jj] = g_beff[l + 32 * jj];
    #pragma unroll
    for (int i = 0; i < 8; ++i) {
        int row = r0 + w * 8 + i;
        float ns = 0.f;
        #pragma unroll
        for (int jj = 0; jj < 4; ++jj) {
            int col = l + 32 * jj;
            float y = lo32(acc[i][jj]) + hi32(acc[i][jj]) + be[jj];
            __half hi = __float2half_rn(y);
            float lof = y - __half2float(hi);
            g_y2[(size_t)row * SK + col]      = hi;
            g_y2[(size_t)row * SK + HP + col] = __float2half_rn(lof);
            ns += y * y;
        }
        #pragma unroll
        for (int off = 16; off; off >>= 1) ns += __shfl_xor_sync(0xffffffffu, ns, off);
        if (l == 0) g_norm[row] = ns;
    }
}

// ---------------------------------------------------------------------------
// Kernel 3 (mma.sync f16): per CTA 128 rows x all 2048 cols (16 tiles of 128).
// dot = hi.hi + lo.hi (16 k-steps; hi.lo dropped: ~7e-5 rel, lo.lo ~1e-7).
// B tiles carry only the hi half (32KB). B frags hoisted (8 chunks, 64 regs).
// Fused exp epilogue + rowsum + coalesced rescale.
// ---------------------------------------------------------------------------
static __device__ __forceinline__ void load_tileA(uint32_t sbase, const char* g0, int tid) {
    #pragma unroll
    for (int it = 0; it < 16; ++it) {
        int idx = tid + it * 256;           // 4096 chunks: 128 rows x 512B
        int r = idx >> 5;
        int c = idx & 31;
        cpa16(sbase + r * 512 + ((c ^ (r & 7)) << 4), g0 + (size_t)r * 512 + (size_t)c * 16);
    }
}
static __device__ __forceinline__ void load_tileB(uint32_t sbase, const char* g0, int tid) {
    #pragma unroll
    for (int it = 0; it < 8; ++it) {
        int idx = tid + it * 256;           // 2048 chunks: 128 rows x 256B (hi half)
        int r = idx >> 4;
        int c = idx & 15;
        cpa16(sbase + r * 256 + ((c ^ (r & 7)) << 4), g0 + (size_t)r * 512 + (size_t)c * 16);
    }
}

__global__ __launch_bounds__(256, 1) void score_kernel(const float* __restrict__ pid,
                                                       float* __restrict__ out) {
    extern __shared__ unsigned char dsm[];
    __shared__ float s_cn[LL];    // cA * norm for the whole batch
    __shared__ float s_rs[128];   // rowsums -> reciprocals

    const int tid = threadIdx.x, w = tid >> 5, l = tid & 31;
    const int b    = blockIdx.x >> 4;
    const int tile = blockIdx.x & 15;
    const int rb   = tile * 128;            // row base within batch
    const int wm = w & 1, wn = w >> 1;

    uint32_t abase = (smem_u32(dsm) + 1023) & ~1023u;
    uint32_t bbuf[2] = { abase + 65536u, abase + 98304u };

    const char* Yrow = (const char*)(g_y2 + (size_t)(b * LL + rb) * SK);
    const char* Ybat = (const char*)(g_y2 + (size_t)b * LL * SK);

    load_tileA(abase, Yrow, tid);
    load_tileB(bbuf[0], Ybat, tid);
    cpa_commit();

    const float p  = pid[0];
    const float cA = -0.5f * p * p * LOG2E;
    const float a2 = -2.f * cA;
    #pragma unroll
    for (int i = 0; i < 8; ++i) s_cn[tid + i * 256] = cA * g_norm[b * LL + tid + i * 256];
    if (tid < 128) s_rs[tid] = 0.f;

    // ldmatrix address precompute
    const int g = l >> 3;
    uint32_t aAddr[4], aSwz[4];
    #pragma unroll
    for (int mf = 0; mf < 4; ++mf) {
        int row = wm * 64 + mf * 16 + (l & 7) + ((g & 1) * 8);
        aAddr[mf] = abase + row * 512;
        aSwz[mf]  = row & 7;
    }
    const uint32_t ghA = (uint32_t)(g >> 1);
    uint32_t bRow[2], bSwz[2];
    #pragma unroll
    for (int nf2 = 0; nf2 < 2; ++nf2) {
        int row = wn * 32 + nf2 * 16 + (l & 7) + ((g >> 1) * 8);
        bRow[nf2] = (uint32_t)row * 256;    // B rows are 256B (hi half only)
        bSwz[nf2] = row & 7;
    }
    const uint32_t ghB = (uint32_t)(g & 1);

    cpa_wait0();
    __syncthreads();

    // per-thread row constants (+ fold log2(log2 e) so e = ex2(ex2(arg)))
    float cni[4][2];
    #pragma unroll
    for (int mf = 0; mf < 4; ++mf) {
        int r0l = wm * 64 + mf * 16 + (l >> 2);
        cni[mf][0] = s_cn[rb + r0l]     + LOG2LOG2E;
        cni[mf][1] = s_cn[rb + r0l + 8] + LOG2LOG2E;
    }

    float part[8];
    #pragma unroll
    for (int i = 0; i < 8; ++i) part[i] = 0.f;

    #pragma unroll 1
    for (int t = 0; t < 16; ++t) {
        if (t < 15) {
            load_tileB(bbuf[(t + 1) & 1], Ybat + (size_t)(t + 1) * 128 * 512, tid);
            cpa_commit();
        }

        float acc[4][4][4];
        #pragma unroll
        for (int mf = 0; mf < 4; ++mf)
            #pragma unroll
            for (int nf = 0; nf < 4; ++nf)
                #pragma unroll
                for (int k = 0; k < 4; ++k) acc[mf][nf][k] = 0.f;

        const uint32_t bb = bbuf[t & 1];

        // hoist all B fragments (hi chunks 0..7) once per tile
        uint32_t bfr[8][2][4];
        #pragma unroll
        for (int kb = 0; kb < 8; ++kb)
            #pragma unroll
            for (int nf2 = 0; nf2 < 2; ++nf2)
                ldsm4(bfr[kb][nf2][0], bfr[kb][nf2][1], bfr[kb][nf2][2], bfr[kb][nf2][3],
                      bb + bRow[nf2] + ((((uint32_t)kb * 2 + ghB) ^ bSwz[nf2]) << 4));

        // 16 k-steps: s<8: A=hi(kA=s); s>=8: A=lo(kA=s); B chunk = s&7 (hi)
        #pragma unroll
        for (int s = 0; s < 16; ++s) {
            const int kb = s & 7;
            uint32_t a[4][4];
            #pragma unroll
            for (int mf = 0; mf < 4; ++mf)
                ldsm4(a[mf][0], a[mf][1], a[mf][2], a[mf][3],
                      aAddr[mf] + ((((uint32_t)s * 2 + ghA) ^ aSwz[mf]) << 4));
            #pragma unroll
            for (int mf = 0; mf < 4; ++mf) {
                mma16816(acc[mf][0], a[mf], &bfr[kb][0][0]);
                mma16816(acc[mf][1], a[mf], &bfr[kb][0][2]);
                mma16816(acc[mf][2], a[mf], &bfr[kb][1][0]);
                mma16816(acc[mf][3], a[mf], &bfr[kb][1][2]);
            }
        }

        // epilogue: e = ex2(ex2(a2*dot + cni' + cnj)), store, rowsum partials
        #pragma unroll
        for (int nf = 0; nf < 4; ++nf) {
            int cl = wn * 32 + nf * 8 + (l & 3) * 2;
            float cnj0 = s_cn[t * 128 + cl];
            float cnj1 = s_cn[t * 128 + cl + 1];
            #pragma unroll
            for (int mf = 0; mf < 4; ++mf) {
                int r0l = wm * 64 + mf * 16 + (l >> 2);
                float e00 = ex2(ex2(fmaf(a2, acc[mf][nf][0], cni[mf][0] + cnj0)));
                float e01 = ex2(ex2(fmaf(a2, acc[mf][nf][1], cni[mf][0] + cnj1)));
                float e10 = ex2(ex2(fmaf(a2, acc[mf][nf][2], cni[mf][1] + cnj0)));
                float e11 = ex2(ex2(fmaf(a2, acc[mf][nf][3], cni[mf][1] + cnj1)));
                part[mf * 2]     += e00 + e01;
                part[mf * 2 + 1] += e10 + e11;
                float* o0 = out + (size_t)(b * LL + rb + r0l) * LL + t * 128 + cl;
                *(float2*)o0            = make_float2(e00, e01);
                *(float2*)(o0 + 8 * LL) = make_float2(e10, e11);
            }
        }

        if (t < 15) {
            cpa_wait0();
            __syncthreads();
        }
    }

    // rowsum reduce: lanes 0..3 within each quad share rows
    #pragma unroll
    for (int i = 0; i < 8; ++i) {
        float v = part[i];
        v += __shfl_xor_sync(0xffffffffu, v, 1);
        v += __shfl_xor_sync(0xffffffffu, v, 2);
        if ((l & 3) == 0) {
            int r0l = wm * 64 + (i >> 1) * 16 + (l >> 2) + (i & 1) * 8;
            atomicAdd(&s_rs[r0l], v);
        }
    }
    __syncthreads();
    if (tid < 128) {
        float inv; asm("rcp.approx.ftz.f32 %0, %1;" : "=f"(inv) : "f"(s_rs[tid]));
        s_rs[tid] = inv;
    }
    __syncthreads();

    // fused normalize, fully coalesced: 65536 f4 per CTA block
    {
        float4* o4 = (float4*)out + (size_t)(b * LL + rb) * 512;
        #pragma unroll 4
        for (int it = 0; it < 256; ++it) {
            int idx = it * 256 + tid;
            float inv = s_rs[idx >> 9];
            float4 v = o4[idx];
            v.x *= inv; v.y *= inv; v.z *= inv; v.w *= inv;
            o4[idx] = v;
        }
    }
}

extern "C" void kernel_launch(void* const* d_in, const int* in_sizes, int n_in,
                              void* d_out, int out_size) {
    const float* q   = (const float*)d_in[0];
    const float* qw  = (const float*)d_in[2];
    const float* qb  = (const float*)d_in[3];
    const float* W   = (const float*)d_in[4];
    const float* pid = (const float*)d_in[5];
    float* out = (float*)d_out;

    cudaFuncSetAttribute(prep_kernel,  cudaFuncAttributeMaxDynamicSharedMemorySize, 65280);
    cudaFuncSetAttribute(proj_kernel,  cudaFuncAttributeMaxDynamicSharedMemorySize, 49152);
    cudaFuncSetAttribute(score_kernel, cudaFuncAttributeMaxDynamicSharedMemorySize, 132096);

    prep_kernel<<<128, 256, 65280>>>(qw, qb, W);
    proj_kernel<<<256, 256, 49152>>>(q);
    score_kernel<<<128, 256, 132096>>>(pid, out);
}

// round 8
// speedup vs baseline: 1.7147x; 1.0042x over previous
#include <cuda_runtime.h>
#include <cuda_fp16.h>
#include <cstdint>

#define BB 8
#define LL 2048
#define DD 1024
#define HH 120
#define HP 128
#define SK 256   // stored split: [hi(128) | lo(128)] fp16
#define LOG2E 1.44269504088896340736f
#define LOG2LOG2E 0.5287663729448977f

// Scratch (device globals; no allocs allowed)
__device__ float g_WeffT[HP * DD];                              // [128][1024]
__device__ float g_beff[HP];
__device__ __align__(256) __half g_y2[(size_t)BB * LL * SK];    // [16384][256] hi|lo
__device__ float g_norm[BB * LL];

// ---------------- PTX helpers ----------------
static __device__ __forceinline__ void fma2(unsigned long long &c,
                                            unsigned long long a,
                                            unsigned long long b) {
    asm("fma.rn.f32x2 %0, %1, %2, %0;" : "+l"(c) : "l"(a), "l"(b));
}
static __device__ __forceinline__ float ex2(float x) {
    float r; asm("ex2.approx.ftz.f32 %0, %1;" : "=f"(r) : "f"(x)); return r;
}
static __device__ __forceinline__ float lo32(unsigned long long v) {
    return __uint_as_float((unsigned)(v & 0xffffffffull));
}
static __device__ __forceinline__ float hi32(unsigned long long v) {
    return __uint_as_float((unsigned)(v >> 32));
}
static __device__ __forceinline__ uint32_t smem_u32(const void* p) {
    uint32_t a;
    asm("{ .reg .u64 t; cvta.to.shared.u64 t, %1; cvt.u32.u64 %0, t; }" : "=r"(a) : "l"(p));
    return a;
}
static __device__ __forceinline__ void cpa16(uint32_t s, const void* g) {
    asm volatile("cp.async.cg.shared.global [%0], [%1], 16;" :: "r"(s), "l"(g));
}
static __device__ __forceinline__ void cpa_commit() { asm volatile("cp.async.commit_group;" ::: "memory"); }
static __device__ __forceinline__ void cpa_wait0()  { asm volatile("cp.async.wait_group 0;" ::: "memory"); }
static __device__ __forceinline__ void ldsm4(uint32_t& r0, uint32_t& r1, uint32_t& r2, uint32_t& r3,
                                             uint32_t addr) {
    asm volatile("ldmatrix.sync.aligned.m8n8.x4.shared.b16 {%0,%1,%2,%3}, [%4];"
                 : "=r"(r0), "=r"(r1), "=r"(r2), "=r"(r3) : "r"(addr));
}
static __device__ __forceinline__ void mma16816(float* d, const uint32_t* a, const uint32_t* b) {
    asm volatile("mma.sync.aligned.m16n8k16.row.col.f32.f16.f16.f32 "
                 "{%0,%1,%2,%3}, {%4,%5,%6,%7}, {%8,%9}, {%0,%1,%2,%3};"
                 : "+f"(d[0]), "+f"(d[1]), "+f"(d[2]), "+f"(d[3])
                 : "r"(a[0]), "r"(a[1]), "r"(a[2]), "r"(a[3]), "r"(b[0]), "r"(b[1]));
}

// ---------------------------------------------------------------------------
// Kernel 1: Weff^T[j][d] = sum_h qW[h][d] * W[h][j];  beff = qb @ W
// Smem-tiled: W (zero-padded to [120][128]) fully resident; 128 CTAs x 8 d-cols.
// ---------------------------------------------------------------------------
__global__ __launch_bounds__(256) void prep_kernel(const float* __restrict__ qw,
                                                   const float* __restrict__ qb,
                                                   const float* __restrict__ W) {
    extern __shared__ float ps[];          // Wp[120*128] + qs[120*8]
    float* Wp = ps;
    float* qs = ps + HH * HP;
    const int tid = threadIdx.x;
    const int d0 = blockIdx.x * 8;

    for (int i = tid; i < HH * HP; i += 256) {
        int j = i & 127;
        Wp[i] = (j < HH) ? W[(i >> 7) * HH + j] : 0.f;
    }
    for (int i = tid; i < HH * 8; i += 256)
        qs[i] = qw[(i >> 3) * DD + d0 + (i & 7)];
    __syncthreads();

    const int j = tid >> 1, dh = (tid & 1) * 4;
    float4 acc = make_float4(0.f, 0.f, 0.f, 0.f);
    #pragma unroll 8
    for (int h = 0; h < HH; ++h) {
        float wv = Wp[h * HP + j];
        float4 qv = *(const float4*)(qs + h * 8 + dh);
        acc.x += wv * qv.x; acc.y += wv * qv.y;
        acc.z += wv * qv.z; acc.w += wv * qv.w;
    }
    *(float4*)(g_WeffT + (size_t)j * DD + d0 + dh) = acc;

    if (blockIdx.x == 0 && tid < HP) {
        float a = 0.f;
        #pragma unroll 8
        for (int h = 0; h < HH; ++h) a += qb[h] * Wp[h * HP + tid];
        g_beff[tid] = a;
    }
}

// ---------------------------------------------------------------------------
// Kernel 2: y = q @ WeffT^T + beff; writes fp16 hi/lo split + fp32 row norms.
// ---------------------------------------------------------------------------
__global__ __launch_bounds__(256, 2) void proj_kernel(const float* __restrict__ q) {
    extern __shared__ __align__(16) unsigned char smem_raw[];
    ulonglong2* As = (ulonglong2*)smem_raw;   // [64][16] f4
    ulonglong2* Bs = As + 64 * 16;            // [128][16] f4

    int tid = threadIdx.x, w = tid >> 5, l = tid & 31;
    int r0 = blockIdx.x * 64;
    const float4* qf4 = (const float4*)q;
    const float4* wf4 = (const float4*)g_WeffT;

    unsigned long long acc[8][4];
    #pragma unroll
    for (int i = 0; i < 8; ++i)
        #pragma unroll
        for (int jj = 0; jj < 4; ++jj) acc[i][jj] = 0ull;

    for (int kc = 0; kc < 16; ++kc) {
        __syncthreads();
        #pragma unroll
        for (int it = 0; it < 4; ++it) {
            int idx = tid + it * 256;
            int r = idx >> 4, g = idx & 15;
            ((float4*)As)[r * 16 + (g ^ (r & 7))] = qf4[(size_t)(r0 + r) * 256 + kc * 16 + g];
        }
        #pragma unroll
        for (int it = 0; it < 8; ++it) {
            int idx = tid + it * 256;
            int r = idx >> 4, g = idx & 15;
            ((float4*)Bs)[r * 16 + (g ^ (r & 7))] = wf4[(size_t)r * 256 + kc * 16 + g];
        }
        __syncthreads();

        #pragma unroll 4
        for (int g4 = 0; g4 < 16; ++g4) {
            ulonglong2 bv[4];
            #pragma unroll
            for (int jj = 0; jj < 4; ++jj) {
                int r = l + 32 * jj;
                bv[jj] = Bs[r * 16 + (g4 ^ (r & 7))];
            }
            #pragma unroll
            for (int i = 0; i < 8; ++i) {
                int r = w * 8 + i;
                ulonglong2 av = As[r * 16 + (g4 ^ (r & 7))];
                #pragma unroll
                for (int jj = 0; jj < 4; ++jj) {
                    fma2(acc[i][jj], av.x, bv[jj].x);
                    fma2(acc[i][jj], av.y, bv[jj].y);
                }
            }
        }
    }

    float be[4];
    #pragma unroll
    for (int jj = 0; jj < 4; ++jj) be[jj] = g_beff[l + 32 * jj];
    #pragma unroll
    for (int i = 0; i < 8; ++i) {
        int row = r0 + w * 8 + i;
        float ns = 0.f;
        #pragma unroll
        for (int jj = 0; jj < 4; ++jj) {
            int col = l + 32 * jj;
            float y = lo32(acc[i][jj]) + hi32(acc[i][jj]) + be[jj];
            __half hi = __float2half_rn(y);
            float lof = y - __half2float(hi);
            g_y2[(size_t)row * SK + col]      = hi;
            g_y2[(size_t)row * SK + HP + col] = __float2half_rn(lof);
            ns += y * y;
        }
        #pragma unroll
        for (int off = 16; off; off >>= 1) ns += __shfl_xor_sync(0xffffffffu, ns, off);
        if (l == 0) g_norm[row] = ns;
    }
}

// ---------------------------------------------------------------------------
// Kernel 3 (mma.sync f16): per CTA 128 rows x all 2048 cols (16 tiles of 128).
// dot = hi.hi + lo.hi (16 k-steps; hi.lo dropped: ~7e-5 rel, lo.lo ~1e-7).
// B tiles carry only the hi half (32KB). B frags hoisted (8 chunks, 64 regs).
// Fused exp epilogue + rowsum + coalesced rescale.
// ---------------------------------------------------------------------------
static __device__ __forceinline__ void load_tileA(uint32_t sbase, const char* g0, int tid) {
    #pragma unroll
    for (int it = 0; it < 16; ++it) {
        int idx = tid + it * 256;           // 4096 chunks: 128 rows x 512B
        int r = idx >> 5;
        int c = idx & 31;
        cpa16(sbase + r * 512 + ((c ^ (r & 7)) << 4), g0 + (size_t)r * 512 + (size_t)c * 16);
    }
}
static __device__ __forceinline__ void load_tileB(uint32_t sbase, const char* g0, int tid) {
    #pragma unroll
    for (int it = 0; it < 8; ++it) {
        int idx = tid + it * 256;           // 2048 chunks: 128 rows x 256B (hi half)
        int r = idx >> 4;
        int c = idx & 15;
        cpa16(sbase + r * 256 + ((c ^ (r & 7)) << 4), g0 + (size_t)r * 512 + (size_t)c * 16);
    }
}

__global__ __launch_bounds__(256, 1) void score_kernel(const float* __restrict__ pid,
                                                       float* __restrict__ out) {
    extern __shared__ unsigned char dsm[];
    __shared__ float s_cn[LL];    // cA * norm for the whole batch
    __shared__ float s_rs[128];   // rowsums -> reciprocals

    const int tid = threadIdx.x, w = tid >> 5, l = tid & 31;
    const int b    = blockIdx.x >> 4;
    const int tile = blockIdx.x & 15;
    const int rb   = tile * 128;            // row base within batch
    const int wm = w & 1, wn = w >> 1;

    uint32_t abase = (smem_u32(dsm) + 1023) & ~1023u;
    uint32_t bbuf[2] = { abase + 65536u, abase + 98304u };

    const char* Yrow = (const char*)(g_y2 + (size_t)(b * LL + rb) * SK);
    const char* Ybat = (const char*)(g_y2 + (size_t)b * LL * SK);

    load_tileA(abase, Yrow, tid);
    load_tileB(bbuf[0], Ybat, tid);
    cpa_commit();

    const float p  = pid[0];
    const float cA = -0.5f * p * p * LOG2E;
    const float a2 = -2.f * cA;
    #pragma unroll
    for (int i = 0; i < 8; ++i) s_cn[tid + i * 256] = cA * g_norm[b * LL + tid + i * 256];
    if (tid < 128) s_rs[tid] = 0.f;

    // ldmatrix address precompute
    const int g = l >> 3;
    uint32_t aAddr[4], aSwz[4];
    #pragma unroll
    for (int mf = 0; mf < 4; ++mf) {
        int row = wm * 64 + mf * 16 + (l & 7) + ((g & 1) * 8);
        aAddr[mf] = abase + row * 512;
        aSwz[mf]  = row & 7;
    }
    const uint32_t ghA = (uint32_t)(g >> 1);
    uint32_t bRow[2], bSwz[2];
    #pragma unroll
    for (int nf2 = 0; nf2 < 2; ++nf2) {
        int row = wn * 32 + nf2 * 16 + (l & 7) + ((g >> 1) * 8);
        bRow[nf2] = (uint32_t)row * 256;    // B rows are 256B (hi half only)
        bSwz[nf2] = row & 7;
    }
    const uint32_t ghB = (uint32_t)(g & 1);

    cpa_wait0();
    __syncthreads();

    // per-thread row constants (+ fold log2(log2 e) so e = ex2(ex2(arg)))
    float cni[4][2];
    #pragma unroll
    for (int mf = 0; mf < 4; ++mf) {
        int r0l = wm * 64 + mf * 16 + (l >> 2);
        cni[mf][0] = s_cn[rb + r0l]     + LOG2LOG2E;
        cni[mf][1] = s_cn[rb + r0l + 8] + LOG2LOG2E;
    }

    float part[8];
    #pragma unroll
    for (int i = 0; i < 8; ++i) part[i] = 0.f;

    #pragma unroll 1
    for (int t = 0; t < 16; ++t) {
        if (t < 15) {
            load_tileB(bbuf[(t + 1) & 1], Ybat + (size_t)(t + 1) * 128 * 512, tid);
            cpa_commit();
        }

        float acc[4][4][4];
        #pragma unroll
        for (int mf = 0; mf < 4; ++mf)
            #pragma unroll
            for (int nf = 0; nf < 4; ++nf)
                #pragma unroll
                for (int k = 0; k < 4; ++k) acc[mf][nf][k] = 0.f;

        const uint32_t bb = bbuf[t & 1];

        // hoist all B fragments (hi chunks 0..7) once per tile
        uint32_t bfr[8][2][4];
        #pragma unroll
        for (int kb = 0; kb < 8; ++kb)
            #pragma unroll
            for (int nf2 = 0; nf2 < 2; ++nf2)
                ldsm4(bfr[kb][nf2][0], bfr[kb][nf2][1], bfr[kb][nf2][2], bfr[kb][nf2][3],
                      bb + bRow[nf2] + ((((uint32_t)kb * 2 + ghB) ^ bSwz[nf2]) << 4));

        // 16 k-steps: s<8: A=hi(kA=s); s>=8: A=lo(kA=s); B chunk = s&7 (hi)
        #pragma unroll
        for (int s = 0; s < 16; ++s) {
            const int kb = s & 7;
            uint32_t a[4][4];
            #pragma unroll
            for (int mf = 0; mf < 4; ++mf)
                ldsm4(a[mf][0], a[mf][1], a[mf][2], a[mf][3],
                      aAddr[mf] + ((((uint32_t)s * 2 + ghA) ^ aSwz[mf]) << 4));
            #pragma unroll
            for (int mf = 0; mf < 4; ++mf) {
                mma16816(acc[mf][0], a[mf], &bfr[kb][0][0]);
                mma16816(acc[mf][1], a[mf], &bfr[kb][0][2]);
                mma16816(acc[mf][2], a[mf], &bfr[kb][1][0]);
                mma16816(acc[mf][3], a[mf], &bfr[kb][1][2]);
            }
        }

        // epilogue: e = ex2(ex2(a2*dot + cni' + cnj)), store, rowsum partials
        #pragma unroll
        for (int nf = 0; nf < 4; ++nf) {
            int cl = wn * 32 + nf * 8 + (l & 3) * 2;
            float cnj0 = s_cn[t * 128 + cl];
            float cnj1 = s_cn[t * 128 + cl + 1];
            #pragma unroll
            for (int mf = 0; mf < 4; ++mf) {
                int r0l = wm * 64 + mf * 16 + (l >> 2);
                float e00 = ex2(ex2(fmaf(a2, acc[mf][nf][0], cni[mf][0] + cnj0)));
                float e01 = ex2(ex2(fmaf(a2, acc[mf][nf][1], cni[mf][0] + cnj1)));
                float e10 = ex2(ex2(fmaf(a2, acc[mf][nf][2], cni[mf][1] + cnj0)));
                float e11 = ex2(ex2(fmaf(a2, acc[mf][nf][3], cni[mf][1] + cnj1)));
                part[mf * 2]     += e00 + e01;
                part[mf * 2 + 1] += e10 + e11;
                float* o0 = out + (size_t)(b * LL + rb + r0l) * LL + t * 128 + cl;
                *(float2*)o0            = make_float2(e00, e01);
                *(float2*)(o0 + 8 * LL) = make_float2(e10, e11);
            }
        }

        if (t < 15) {
            cpa_wait0();
            __syncthreads();
        }
    }

    // rowsum reduce: lanes 0..3 within each quad share rows
    #pragma unroll
    for (int i = 0; i < 8; ++i) {
        float v = part[i];
        v += __shfl_xor_sync(0xffffffffu, v, 1);
        v += __shfl_xor_sync(0xffffffffu, v, 2);
        if ((l & 3) == 0) {
            int r0l = wm * 64 + (i >> 1) * 16 + (l >> 2) + (i & 1) * 8;
            atomicAdd(&s_rs[r0l], v);
        }
    }
    __syncthreads();
    if (tid < 128) {
        float inv; asm("rcp.approx.ftz.f32 %0, %1;" : "=f"(inv) : "f"(s_rs[tid]));
        s_rs[tid] = inv;
    }
    __syncthreads();

    // fused normalize, fully coalesced: 65536 f4 per CTA block
    {
        float4* o4 = (float4*)out + (size_t)(b * LL + rb) * 512;
        #pragma unroll 4
        for (int it = 0; it < 256; ++it) {
            int idx = it * 256 + tid;
            float inv = s_rs[idx >> 9];
            float4 v = o4[idx];
            v.x *= inv; v.y *= inv; v.z *= inv; v.w *= inv;
            o4[idx] = v;
        }
    }
}

extern "C" void kernel_launch(void* const* d_in, const int* in_sizes, int n_in,
                              void* d_out, int out_size) {
    const float* q   = (const float*)d_in[0];
    const float* qw  = (const float*)d_in[2];
    const float* qb  = (const float*)d_in[3];
    const float* W   = (const float*)d_in[4];
    const float* pid = (const float*)d_in[5];
    float* out = (float*)d_out;

    cudaFuncSetAttribute(prep_kernel,  cudaFuncAttributeMaxDynamicSharedMemorySize, 65280);
    cudaFuncSetAttribute(proj_kernel,  cudaFuncAttributeMaxDynamicSharedMemorySize, 49152);
    cudaFuncSetAttribute(score_kernel, cudaFuncAttributeMaxDynamicSharedMemorySize, 132096);

    prep_kernel<<<128, 256, 65280>>>(qw, qb, W);
    proj_kernel<<<256, 256, 49152>>>(q);
    score_kernel<<<128, 256, 132096>>>(pid, out);
}

// round 9
// speedup vs baseline: 1.7181x; 1.0020x over previous
#include <cuda_runtime.h>
#include <cuda_fp16.h>
#include <cstdint>

#define BB 8
#define LL 2048
#define DD 1024
#define HH 120
#define HP 128
#define SK 256   // stored split: [hi(128) | lo(128)] fp16
#define LOG2E 1.44269504088896340736f
#define LOG2LOG2E 0.5287663729448977f

// Scratch (device globals; no allocs allowed)
__device__ float g_WeffT[HP * DD];                              // [128][1024]
__device__ float g_beff[HP];
__device__ __align__(256) __half g_y2[(size_t)BB * LL * SK];    // [16384][256] hi|lo
__device__ float g_norm[BB * LL];

// ---------------- PTX helpers ----------------
static __device__ __forceinline__ void fma2(unsigned long long &c,
                                            unsigned long long a,
                                            unsigned long long b) {
    asm("fma.rn.f32x2 %0, %1, %2, %0;" : "+l"(c) : "l"(a), "l"(b));
}
static __device__ __forceinline__ float ex2(float x) {
    float r; asm("ex2.approx.ftz.f32 %0, %1;" : "=f"(r) : "f"(x)); return r;
}
static __device__ __forceinline__ float lo32(unsigned long long v) {
    return __uint_as_float((unsigned)(v & 0xffffffffull));
}
static __device__ __forceinline__ float hi32(unsigned long long v) {
    return __uint_as_float((unsigned)(v >> 32));
}
static __device__ __forceinline__ uint32_t smem_u32(const void* p) {
    uint32_t a;
    asm("{ .reg .u64 t; cvta.to.shared.u64 t, %1; cvt.u32.u64 %0, t; }" : "=r"(a) : "l"(p));
    return a;
}
static __device__ __forceinline__ void cpa16(uint32_t s, const void* g) {
    asm volatile("cp.async.cg.shared.global [%0], [%1], 16;" :: "r"(s), "l"(g));
}
static __device__ __forceinline__ void cpa_commit() { asm volatile("cp.async.commit_group;" ::: "memory"); }
static __device__ __forceinline__ void cpa_wait0()  { asm volatile("cp.async.wait_group 0;" ::: "memory"); }
static __device__ __forceinline__ void ldsm4(uint32_t& r0, uint32_t& r1, uint32_t& r2, uint32_t& r3,
                                             uint32_t addr) {
    asm volatile("ldmatrix.sync.aligned.m8n8.x4.shared.b16 {%0,%1,%2,%3}, [%4];"
                 : "=r"(r0), "=r"(r1), "=r"(r2), "=r"(r3) : "r"(addr));
}
static __device__ __forceinline__ void mma16816(float* d, const uint32_t* a, const uint32_t* b) {
    asm volatile("mma.sync.aligned.m16n8k16.row.col.f32.f16.f16.f32 "
                 "{%0,%1,%2,%3}, {%4,%5,%6,%7}, {%8,%9}, {%0,%1,%2,%3};"
                 : "+f"(d[0]), "+f"(d[1]), "+f"(d[2]), "+f"(d[3])
                 : "r"(a[0]), "r"(a[1]), "r"(a[2]), "r"(a[3]), "r"(b[0]), "r"(b[1]));
}

// ---------------------------------------------------------------------------
// Kernel 1: Weff^T[j][d] = sum_h qW[h][d] * W[h][j];  beff = qb @ W
// Smem-tiled: W (zero-padded to [120][128]) fully resident; 128 CTAs x 8 d-cols.
// ---------------------------------------------------------------------------
__global__ __launch_bounds__(256) void prep_kernel(const float* __restrict__ qw,
                                                   const float* __restrict__ qb,
                                                   const float* __restrict__ W) {
    extern __shared__ float ps[];          // Wp[120*128] + qs[120*8]
    float* Wp = ps;
    float* qs = ps + HH * HP;
    const int tid = threadIdx.x;
    const int d0 = blockIdx.x * 8;

    for (int i = tid; i < HH * HP; i += 256) {
        int j = i & 127;
        Wp[i] = (j < HH) ? W[(i >> 7) * HH + j] : 0.f;
    }
    for (int i = tid; i < HH * 8; i += 256)
        qs[i] = qw[(i >> 3) * DD + d0 + (i & 7)];
    __syncthreads();

    const int j = tid >> 1, dh = (tid & 1) * 4;
    float4 acc = make_float4(0.f, 0.f, 0.f, 0.f);
    #pragma unroll 8
    for (int h = 0; h < HH; ++h) {
        float wv = Wp[h * HP + j];
        float4 qv = *(const float4*)(qs + h * 8 + dh);
        acc.x += wv * qv.x; acc.y += wv * qv.y;
        acc.z += wv * qv.z; acc.w += wv * qv.w;
    }
    *(float4*)(g_WeffT + (size_t)j * DD + d0 + dh) = acc;

    if (blockIdx.x == 0 && tid < HP) {
        float a = 0.f;
        #pragma unroll 8
        for (int h = 0; h < HH; ++h) a += qb[h] * Wp[h * HP + tid];
        g_beff[tid] = a;
    }
}

// ---------------------------------------------------------------------------
// Kernel 2: y = q @ WeffT^T + beff; writes fp16 hi/lo split + fp32 row norms.
// ---------------------------------------------------------------------------
__global__ __launch_bounds__(256, 2) void proj_kernel(const float* __restrict__ q) {
    extern __shared__ __align__(16) unsigned char smem_raw[];
    ulonglong2* As = (ulonglong2*)smem_raw;   // [64][16] f4
    ulonglong2* Bs = As + 64 * 16;            // [128][16] f4

    int tid = threadIdx.x, w = tid >> 5, l = tid & 31;
    int r0 = blockIdx.x * 64;
    const float4* qf4 = (const float4*)q;
    const float4* wf4 = (const float4*)g_WeffT;

    unsigned long long acc[8][4];
    #pragma unroll
    for (int i = 0; i < 8; ++i)
        #pragma unroll
        for (int jj = 0; jj < 4; ++jj) acc[i][jj] = 0ull;

    for (int kc = 0; kc < 16; ++kc) {
        __syncthreads();
        #pragma unroll
        for (int it = 0; it < 4; ++it) {
            int idx = tid + it * 256;
            int r = idx >> 4, g = idx & 15;
            ((float4*)As)[r * 16 + (g ^ (r & 7))] = qf4[(size_t)(r0 + r) * 256 + kc * 16 + g];
        }
        #pragma unroll
        for (int it = 0; it < 8; ++it) {
            int idx = tid + it * 256;
            int r = idx >> 4, g = idx & 15;
            ((float4*)Bs)[r * 16 + (g ^ (r & 7))] = wf4[(size_t)r * 256 + kc * 16 + g];
        }
        __syncthreads();

        #pragma unroll 4
        for (int g4 = 0; g4 < 16; ++g4) {
            ulonglong2 bv[4];
            #pragma unroll
            for (int jj = 0; jj < 4; ++jj) {
                int r = l + 32 * jj;
                bv[jj] = Bs[r * 16 + (g4 ^ (r & 7))];
            }
            #pragma unroll
            for (int i = 0; i < 8; ++i) {
                int r = w * 8 + i;
                ulonglong2 av = As[r * 16 + (g4 ^ (r & 7))];
                #pragma unroll
                for (int jj = 0; jj < 4; ++jj) {
                    fma2(acc[i][jj], av.x, bv[jj].x);
                    fma2(acc[i][jj], av.y, bv[jj].y);
                }
            }
        }
    }

    float be[4];
    #pragma unroll
    for (int jj = 0; jj < 4; ++jj) be[jj] = g_beff[l + 32 * jj];
    #pragma unroll
    for (int i = 0; i < 8; ++i) {
        int row = r0 + w * 8 + i;
        float ns = 0.f;
        #pragma unroll
        for (int jj = 0; jj < 4; ++jj) {
            int col = l + 32 * jj;
            float y = lo32(acc[i][jj]) + hi32(acc[i][jj]) + be[jj];
            __half hi = __float2half_rn(y);
            float lof = y - __half2float(hi);
            g_y2[(size_t)row * SK + col]      = hi;
            g_y2[(size_t)row * SK + HP + col] = __float2half_rn(lof);
            ns += y * y;
        }
        #pragma unroll
        for (int off = 16; off; off >>= 1) ns += __shfl_xor_sync(0xffffffffu, ns, off);
        if (l == 0) g_norm[row] = ns;
    }
}

// ---------------------------------------------------------------------------
// Kernel 3 (mma.sync f16): per CTA 128 rows x all 2048 cols (16 tiles of 128).
// dot = hi.hi + lo.hi (16 k-steps; hi.lo dropped: ~7e-5 rel, lo.lo ~1e-7).
// B tiles carry only the hi half (32KB). B frags hoisted (8 chunks, 64 regs).
// Fused exp epilogue + rowsum + coalesced rescale.
// ---------------------------------------------------------------------------
static __device__ __forceinline__ void load_tileA(uint32_t sbase, const char* g0, int tid) {
    #pragma unroll
    for (int it = 0; it < 16; ++it) {
        int idx = tid + it * 256;           // 4096 chunks: 128 rows x 512B
        int r = idx >> 5;
        int c = idx & 31;
        cpa16(sbase + r * 512 + ((c ^ (r & 7)) << 4), g0 + (size_t)r * 512 + (size_t)c * 16);
    }
}
static __device__ __forceinline__ void load_tileB(uint32_t sbase, const char* g0, int tid) {
    #pragma unroll
    for (int it = 0; it < 8; ++it) {
        int idx = tid + it * 256;           // 2048 chunks: 128 rows x 256B (hi half)
        int r = idx >> 4;
        int c = idx & 15;
        cpa16(sbase + r * 256 + ((c ^ (r & 7)) << 4), g0 + (size_t)r * 512 + (size_t)c * 16);
    }
}

__global__ __launch_bounds__(256, 1) void score_kernel(const float* __restrict__ pid,
                                                       float* __restrict__ out) {
    extern __shared__ unsigned char dsm[];
    __shared__ float s_cn[LL];    // cA * norm for the whole batch
    __shared__ float s_rs[128];   // rowsums -> reciprocals

    const int tid = threadIdx.x, w = tid >> 5, l = tid & 31;
    const int b    = blockIdx.x >> 4;
    const int tile = blockIdx.x & 15;
    const int rb   = tile * 128;            // row base within batch
    const int wm = w & 1, wn = w >> 1;

    uint32_t abase = (smem_u32(dsm) + 1023) & ~1023u;
    uint32_t bbuf[2] = { abase + 65536u, abase + 98304u };

    const char* Yrow = (const char*)(g_y2 + (size_t)(b * LL + rb) * SK);
    const char* Ybat = (const char*)(g_y2 + (size_t)b * LL * SK);

    load_tileA(abase, Yrow, tid);
    load_tileB(bbuf[0], Ybat, tid);
    cpa_commit();

    const float p  = pid[0];
    const float cA = -0.5f * p * p * LOG2E;
    const float a2 = -2.f * cA;
    #pragma unroll
    for (int i = 0; i < 8; ++i) s_cn[tid + i * 256] = cA * g_norm[b * LL + tid + i * 256];
    if (tid < 128) s_rs[tid] = 0.f;

    // ldmatrix address precompute
    const int g = l >> 3;
    uint32_t aAddr[4], aSwz[4];
    #pragma unroll
    for (int mf = 0; mf < 4; ++mf) {
        int row = wm * 64 + mf * 16 + (l & 7) + ((g & 1) * 8);
        aAddr[mf] = abase + row * 512;
        aSwz[mf]  = row & 7;
    }
    const uint32_t ghA = (uint32_t)(g >> 1);
    uint32_t bRow[2], bSwz[2];
    #pragma unroll
    for (int nf2 = 0; nf2 < 2; ++nf2) {
        int row = wn * 32 + nf2 * 16 + (l & 7) + ((g >> 1) * 8);
        bRow[nf2] = (uint32_t)row * 256;    // B rows are 256B (hi half only)
        bSwz[nf2] = row & 7;
    }
    const uint32_t ghB = (uint32_t)(g & 1);

    cpa_wait0();
    __syncthreads();

    // per-thread row constants (+ fold log2(log2 e) so e = ex2(ex2(arg)))
    float cni[4][2];
    #pragma unroll
    for (int mf = 0; mf < 4; ++mf) {
        int r0l = wm * 64 + mf * 16 + (l >> 2);
        cni[mf][0] = s_cn[rb + r0l]     + LOG2LOG2E;
        cni[mf][1] = s_cn[rb + r0l + 8] + LOG2LOG2E;
    }

    float part[8];
    #pragma unroll
    for (int i = 0; i < 8; ++i) part[i] = 0.f;

    #pragma unroll 1
    for (int t = 0; t < 16; ++t) {
        if (t < 15) {
            load_tileB(bbuf[(t + 1) & 1], Ybat + (size_t)(t + 1) * 128 * 512, tid);
            cpa_commit();
        }

        float acc[4][4][4];
        #pragma unroll
        for (int mf = 0; mf < 4; ++mf)
            #pragma unroll
            for (int nf = 0; nf < 4; ++nf)
                #pragma unroll
                for (int k = 0; k < 4; ++k) acc[mf][nf][k] = 0.f;

        const uint32_t bb = bbuf[t & 1];

        // hoist all B fragments (hi chunks 0..7) once per tile
        uint32_t bfr[8][2][4];
        #pragma unroll
        for (int kb = 0; kb < 8; ++kb)
            #pragma unroll
            for (int nf2 = 0; nf2 < 2; ++nf2)
                ldsm4(bfr[kb][nf2][0], bfr[kb][nf2][1], bfr[kb][nf2][2], bfr[kb][nf2][3],
                      bb + bRow[nf2] + ((((uint32_t)kb * 2 + ghB) ^ bSwz[nf2]) << 4));

        // 16 k-steps: s<8: A=hi(kA=s); s>=8: A=lo(kA=s); B chunk = s&7 (hi)
        #pragma unroll
        for (int s = 0; s < 16; ++s) {
            const int kb = s & 7;
            uint32_t a[4][4];
            #pragma unroll
            for (int mf = 0; mf < 4; ++mf)
                ldsm4(a[mf][0], a[mf][1], a[mf][2], a[mf][3],
                      aAddr[mf] + ((((uint32_t)s * 2 + ghA) ^ aSwz[mf]) << 4));
            #pragma unroll
            for (int mf = 0; mf < 4; ++mf) {
                mma16816(acc[mf][0], a[mf], &bfr[kb][0][0]);
                mma16816(acc[mf][1], a[mf], &bfr[kb][0][2]);
                mma16816(acc[mf][2], a[mf], &bfr[kb][1][0]);
                mma16816(acc[mf][3], a[mf], &bfr[kb][1][2]);
            }
        }

        // epilogue: e = ex2(ex2(a2*dot + cni' + cnj)), store, rowsum partials
        #pragma unroll
        for (int nf = 0; nf < 4; ++nf) {
            int cl = wn * 32 + nf * 8 + (l & 3) * 2;
            float cnj0 = s_cn[t * 128 + cl];
            float cnj1 = s_cn[t * 128 + cl + 1];
            #pragma unroll
            for (int mf = 0; mf < 4; ++mf) {
                int r0l = wm * 64 + mf * 16 + (l >> 2);
                float e00 = ex2(ex2(fmaf(a2, acc[mf][nf][0], cni[mf][0] + cnj0)));
                float e01 = ex2(ex2(fmaf(a2, acc[mf][nf][1], cni[mf][0] + cnj1)));
                float e10 = ex2(ex2(fmaf(a2, acc[mf][nf][2], cni[mf][1] + cnj0)));
                float e11 = ex2(ex2(fmaf(a2, acc[mf][nf][3], cni[mf][1] + cnj1)));
                part[mf * 2]     += e00 + e01;
                part[mf * 2 + 1] += e10 + e11;
                float* o0 = out + (size_t)(b * LL + rb + r0l) * LL + t * 128 + cl;
                *(float2*)o0            = make_float2(e00, e01);
                *(float2*)(o0 + 8 * LL) = make_float2(e10, e11);
            }
        }

        if (t < 15) {
            cpa_wait0();
            __syncthreads();
        }
    }

    // rowsum reduce: lanes 0..3 within each quad share rows
    #pragma unroll
    for (int i = 0; i < 8; ++i) {
        float v = part[i];
        v += __shfl_xor_sync(0xffffffffu, v, 1);
        v += __shfl_xor_sync(0xffffffffu, v, 2);
        if ((l & 3) == 0) {
            int r0l = wm * 64 + (i >> 1) * 16 + (l >> 2) + (i & 1) * 8;
            atomicAdd(&s_rs[r0l], v);
        }
    }
    __syncthreads();
    if (tid < 128) {
        float inv; asm("rcp.approx.ftz.f32 %0, %1;" : "=f"(inv) : "f"(s_rs[tid]));
        s_rs[tid] = inv;
    }
    __syncthreads();

    // fused normalize, fully coalesced: 65536 f4 per CTA block
    {
        float4* o4 = (float4*)out + (size_t)(b * LL + rb) * 512;
        #pragma unroll 4
        for (int it = 0; it < 256; ++it) {
            int idx = it * 256 + tid;
            float inv = s_rs[idx >> 9];
            float4 v = o4[idx];
            v.x *= inv; v.y *= inv; v.z *= inv; v.w *= inv;
            o4[idx] = v;
        }
    }
}

extern "C" void kernel_launch(void* const* d_in, const int* in_sizes, int n_in,
                              void* d_out, int out_size) {
    const float* q   = (const float*)d_in[0];
    const float* qw  = (const float*)d_in[2];
    const float* qb  = (const float*)d_in[3];
    const float* W   = (const float*)d_in[4];
    const float* pid = (const float*)d_in[5];
    float* out = (float*)d_out;

    cudaFuncSetAttribute(prep_kernel,  cudaFuncAttributeMaxDynamicSharedMemorySize, 65280);
    cudaFuncSetAttribute(proj_kernel,  cudaFuncAttributeMaxDynamicSharedMemorySize, 49152);
    cudaFuncSetAttribute(score_kernel, cudaFuncAttributeMaxDynamicSharedMemorySize, 132096);

    prep_kernel<<<128, 256, 65280>>>(qw, qb, W);
    proj_kernel<<<256, 256, 49152>>>(q);
    score_kernel<<<128, 256, 132096>>>(pid, out);
}